// round 1
// baseline (speedup 1.0000x reference)
#include <cuda_runtime.h>

// FeedForwardQuantum fused kernel (fp32 SIMT baseline):
//   q[m, i]   = cos(x[m, i]) * cos(theta[i]),  i < 8          (rank-8 "quantum" features)
//   h[m, f]   = relu( sum_i q[m,i] * W1[f,i] + b1[f] )        (recomputed per K-tile, never hits gmem)
//   out[m, e] = sum_f h[m,f] * W2[e,f] + b2[e]
//
// Shapes: M = 8*2048 = 16384 tokens, EMB = 1024, FFN = 4096, NQ = 8.
// All dims divide the tile sizes exactly -> no bounds checks.

namespace {
constexpr int Mtot = 8 * 2048;   // 16384
constexpr int EMB  = 1024;       // output cols; also x row stride
constexpr int FFN  = 4096;       // inner K
constexpr int NQ   = 8;

constexpr int BM = 128;
constexpr int BN = 128;
constexpr int BK = 32;
constexpr int NTHREADS = 256;    // 16 x 16 threads, each owns an 8x8 output micro-tile
}

__global__ __launch_bounds__(NTHREADS, 2)
void ffq_fused_kernel(const float* __restrict__ x,
                      const float* __restrict__ theta,
                      const float* __restrict__ W1,   // [FFN, NQ] row-major
                      const float* __restrict__ b1,   // [FFN]
                      const float* __restrict__ W2,   // [EMB, FFN] row-major
                      const float* __restrict__ b2,   // [EMB]
                      float* __restrict__ out)        // [Mtot, EMB]
{
    __shared__ float q_s[BM][NQ];        // 4 KB   (written once)
    __shared__ float hs[BK][BM];         // 16 KB  (h tile, transposed: [k][m])
    __shared__ float ws[BK][BN];         // 16 KB  (W2 tile, transposed: [k][n])
    __shared__ float w1s[BK][NQ];        // 1 KB
    __shared__ float b1s[BK];            // 128 B

    const int tid = threadIdx.x;
    const int m0  = blockIdx.y * BM;
    const int n0  = blockIdx.x * BN;

    // ---- q tile: q_s[m][i] = cos(x[m0+m, i]) * cos(theta[i]) ----
    {
        float ct[NQ];
#pragma unroll
        for (int i = 0; i < NQ; ++i) ct[i] = cosf(__ldg(theta + i));
#pragma unroll
        for (int e = tid; e < BM * NQ; e += NTHREADS) {
            int m = e >> 3, i = e & 7;
            q_s[m][i] = cosf(__ldg(x + (size_t)(m0 + m) * EMB + i)) * ct[i];
        }
    }
    __syncthreads();

    // h-compute mapping: thread owns row hm, k values {hk0 + 2p}
    const int hm  = tid & (BM - 1);   // 0..127
    const int hk0 = tid >> 7;         // 0 or 1

    // main-loop mapping: 8x8 micro-tile
    const int tm = (tid >> 4) * 8;    // row base within tile
    const int tn = (tid & 15) * 8;    // col base within tile

    float acc[8][8];
#pragma unroll
    for (int i = 0; i < 8; ++i)
#pragma unroll
        for (int j = 0; j < 8; ++j) acc[i][j] = 0.0f;

    for (int kt = 0; kt < FFN; kt += BK) {
        // ---- phase A: stage W1 chunk + b1 chunk (disjoint from hs/ws, safe pre-sync) ----
        // W1 rows kt..kt+BK-1 are 256 contiguous floats.
        w1s[tid >> 3][tid & 7] = __ldg(W1 + (size_t)kt * NQ + tid);
        if (tid < BK) b1s[tid] = __ldg(b1 + kt + tid);
        __syncthreads();   // S1: w1s/b1s visible; prior main loop finished reading hs/ws

        // ---- phase B1: h tile (transposed) ----
        {
            float4 qa = *(const float4*)&q_s[hm][0];
            float4 qb = *(const float4*)&q_s[hm][4];
#pragma unroll
            for (int p = 0; p < BK / 2; ++p) {
                int k = hk0 + 2 * p;
                float4 wa = *(const float4*)&w1s[k][0];
                float4 wb = *(const float4*)&w1s[k][4];
                float hv = b1s[k];
                hv = fmaf(qa.x, wa.x, hv);
                hv = fmaf(qa.y, wa.y, hv);
                hv = fmaf(qa.z, wa.z, hv);
                hv = fmaf(qa.w, wa.w, hv);
                hv = fmaf(qb.x, wb.x, hv);
                hv = fmaf(qb.y, wb.y, hv);
                hv = fmaf(qb.z, wb.z, hv);
                hv = fmaf(qb.w, wb.w, hv);
                hs[k][hm] = fmaxf(hv, 0.0f);
            }
        }

        // ---- phase B2: W2 tile -> ws (transposed) ----
#pragma unroll
        for (int p = 0; p < (BM * BK / 4) / NTHREADS; ++p) {   // 4 float4 per thread
            int idx = tid + p * NTHREADS;                      // 0..1023
            int n  = idx >> 3;                                 // 0..127
            int kq = idx & 7;                                  // float4 index within row
            float4 v = *(const float4*)(W2 + (size_t)(n0 + n) * FFN + kt + kq * 4);
            ws[kq * 4 + 0][n] = v.x;
            ws[kq * 4 + 1][n] = v.y;
            ws[kq * 4 + 2][n] = v.z;
            ws[kq * 4 + 3][n] = v.w;
        }
        __syncthreads();   // S2: hs, ws ready

        // ---- phase C: 128x128x32 FMA ----
#pragma unroll
        for (int k = 0; k < BK; ++k) {
            float4 a0 = *(const float4*)&hs[k][tm];
            float4 a1 = *(const float4*)&hs[k][tm + 4];
            float4 c0 = *(const float4*)&ws[k][tn];
            float4 c1 = *(const float4*)&ws[k][tn + 4];
            float a[8] = {a0.x, a0.y, a0.z, a0.w, a1.x, a1.y, a1.z, a1.w};
            float b[8] = {c0.x, c0.y, c0.z, c0.w, c1.x, c1.y, c1.z, c1.w};
#pragma unroll
            for (int i = 0; i < 8; ++i)
#pragma unroll
                for (int j = 0; j < 8; ++j)
                    acc[i][j] = fmaf(a[i], b[j], acc[i][j]);
        }
        __syncthreads();   // protect hs/ws before next iteration overwrites
    }

    // ---- epilogue: + b2, store ----
    float bb[8];
#pragma unroll
    for (int j = 0; j < 8; ++j) bb[j] = __ldg(b2 + n0 + tn + j);

#pragma unroll
    for (int i = 0; i < 8; ++i) {
        float* orow = out + (size_t)(m0 + tm + i) * EMB + n0 + tn;
        float4 v0, v1;
        v0.x = acc[i][0] + bb[0];
        v0.y = acc[i][1] + bb[1];
        v0.z = acc[i][2] + bb[2];
        v0.w = acc[i][3] + bb[3];
        v1.x = acc[i][4] + bb[4];
        v1.y = acc[i][5] + bb[5];
        v1.z = acc[i][6] + bb[6];
        v1.w = acc[i][7] + bb[7];
        *(float4*)(orow)     = v0;
        *(float4*)(orow + 4) = v1;
    }
}

extern "C" void kernel_launch(void* const* d_in, const int* in_sizes, int n_in,
                              void* d_out, int out_size)
{
    const float* x     = (const float*)d_in[0];
    const float* theta = (const float*)d_in[1];
    const float* W1    = (const float*)d_in[2];
    const float* b1    = (const float*)d_in[3];
    const float* W2    = (const float*)d_in[4];
    const float* b2    = (const float*)d_in[5];
    float* out = (float*)d_out;

    dim3 grid(EMB / BN, Mtot / BM);   // (8, 128)
    ffq_fused_kernel<<<grid, NTHREADS>>>(x, theta, W1, b1, W2, b2, out);
}

// round 4
// speedup vs baseline: 2.2446x; 2.2446x over previous
#include <cuda_runtime.h>
#include <cuda_bf16.h>
#include <cstdint>

// ============================================================================
// FeedForwardQuantum via mma.sync bf16x3 (hi/lo error compensation).
//   q[m,i]   = cos(x[m,i]) * cos(theta[i]), i<8
//   h[m,f]   = relu(q @ W1^T + b1)   (recomputed per K-tile, split bf16 hi/lo)
//   out[m,e] = h @ W2^T + b2         (3 HMMA passes: hh + h_hi*W_lo + h_lo*W_hi)
// tcgen05 is unavailable (harness PTX targets sm_103 baseline), so this uses
// mma.sync.m16n8k16 + ldmatrix + cp.async, all baseline-PTX legal.
// ============================================================================

namespace {
constexpr int Mtot = 16384, EMB = 1024, FFN = 4096, NQ = 8;
constexpr int BM = 128, BN = 128, BK = 32;
constexpr int NTILE = FFN / BK;     // 128
constexpr int NTH = 256;            // 8 warps, 2x4 warp grid, 64x32 warp tiles
constexpr int RS = 80;              // smem row stride (bytes): 64B data + 16B pad

// per-stage smem offsets (bytes)
constexpr int S_W1  = 0;            // 32*8*4      = 1024
constexpr int S_B1  = 1024;         // 32*4        = 128
constexpr int S_AHI = 1152;         // 128*80      = 10240
constexpr int S_ALO = 11392;
constexpr int S_BHI = 21632;
constexpr int S_BLO = 31872;
constexpr int STAGE = 42112;

constexpr int OFF_Q  = 0;           // 128*8*4 = 4096
constexpr int OFF_ST = 4096;
constexpr int SMEM_BYTES = OFF_ST + 2 * STAGE;   // 88320
}

// W2 pre-split into bf16 hi/lo (device scratch, filled by pre-kernel)
__device__ __nv_bfloat16 g_w2hi[(size_t)EMB * FFN];
__device__ __nv_bfloat16 g_w2lo[(size_t)EMB * FFN];

// ---------------------------------------------------------------------------
__device__ __forceinline__ uint32_t smem_u32(const void* p) {
    uint32_t a;
    asm("{ .reg .u64 t; cvta.to.shared.u64 t, %1; cvt.u32.u64 %0, t; }"
        : "=r"(a) : "l"(p));
    return a;
}
__device__ __forceinline__ void cp16(uint32_t dst, const void* src) {
    asm volatile("cp.async.cg.shared.global [%0], [%1], 16;\n"
                 :: "r"(dst), "l"(src) : "memory");
}
__device__ __forceinline__ void cp_commit() {
    asm volatile("cp.async.commit_group;\n" ::: "memory");
}
__device__ __forceinline__ void cp_wait_all() {
    asm volatile("cp.async.wait_group 0;\n" ::: "memory");
}
__device__ __forceinline__ void ldsm_x4(uint32_t a, uint32_t* r) {
    asm volatile("ldmatrix.sync.aligned.m8n8.x4.shared.b16 {%0,%1,%2,%3}, [%4];\n"
                 : "=r"(r[0]), "=r"(r[1]), "=r"(r[2]), "=r"(r[3]) : "r"(a));
}
__device__ __forceinline__ void mma_bf16(float* c, const uint32_t* a,
                                         const uint32_t* b) {
    asm volatile(
        "mma.sync.aligned.m16n8k16.row.col.f32.bf16.bf16.f32 "
        "{%0,%1,%2,%3}, {%4,%5,%6,%7}, {%8,%9}, {%0,%1,%2,%3};\n"
        : "+f"(c[0]), "+f"(c[1]), "+f"(c[2]), "+f"(c[3])
        : "r"(a[0]), "r"(a[1]), "r"(a[2]), "r"(a[3]), "r"(b[0]), "r"(b[1]));
}

// ---------------------------------------------------------------------------
// pre-kernel: W2 fp32 -> bf16 hi/lo
// ---------------------------------------------------------------------------
__global__ void w2cvt_kernel(const float* __restrict__ w2) {
    size_t i = (size_t)blockIdx.x * blockDim.x + threadIdx.x;  // float4 index
    float4 v = __ldg((const float4*)w2 + i);
    __nv_bfloat162 ph0, ph1, pl0, pl1;
    ph0.x = __float2bfloat16(v.x); ph0.y = __float2bfloat16(v.y);
    ph1.x = __float2bfloat16(v.z); ph1.y = __float2bfloat16(v.w);
    pl0.x = __float2bfloat16(v.x - __bfloat162float(ph0.x));
    pl0.y = __float2bfloat16(v.y - __bfloat162float(ph0.y));
    pl1.x = __float2bfloat16(v.z - __bfloat162float(ph1.x));
    pl1.y = __float2bfloat16(v.w - __bfloat162float(ph1.y));
    ((uint2*)g_w2hi)[i] = make_uint2(*(uint32_t*)&ph0, *(uint32_t*)&ph1);
    ((uint2*)g_w2lo)[i] = make_uint2(*(uint32_t*)&pl0, *(uint32_t*)&pl1);
}

// ---------------------------------------------------------------------------
// main fused kernel
// ---------------------------------------------------------------------------
__global__ __launch_bounds__(NTH, 1)
void ffq_mma_kernel(const float* __restrict__ x, const float* __restrict__ theta,
                    const float* __restrict__ W1, const float* __restrict__ b1,
                    const float* __restrict__ b2, float* __restrict__ out) {
    extern __shared__ char smem[];
    const uint32_t sb = smem_u32(smem);
    const int tid = threadIdx.x, lane = tid & 31, wid = tid >> 5;
    const int wm = wid >> 2, wn = wid & 3;          // 2x4 warp grid
    const int m0 = blockIdx.y * BM, n0 = blockIdx.x * BN;

    // ---- q tile ----
    float* qs = (float*)(smem + OFF_Q);
    for (int e = tid; e < BM * NQ; e += NTH) {
        int m = e >> 3, i = e & 7;
        qs[e] = cosf(__ldg(x + (size_t)(m0 + m) * EMB + i)) *
                cosf(__ldg(theta + i));
    }

    // ---- cp.async stage issue (W2 hi/lo tile + W1 chunk + b1 chunk) ----
    auto issue_stage = [&](int t) {
        const uint32_t st = sb + OFF_ST + (t & 1) * STAGE;
        const int kt = t * BK;
#pragma unroll
        for (int p = 0; p < 2; ++p) {
            int c = tid + p * 256;                  // 0..511
            int row = c >> 2, seg = c & 3;
            size_t gi = (size_t)(n0 + row) * FFN + kt + seg * 8;
            uint32_t so = row * RS + seg * 16;
            cp16(st + S_BHI + so, g_w2hi + gi);
            cp16(st + S_BLO + so, g_w2lo + gi);
        }
        if (tid < 64)
            cp16(st + S_W1 + tid * 16, W1 + (size_t)kt * NQ + tid * 4);
        else if (tid < 72)
            cp16(st + S_B1 + (tid - 64) * 16, b1 + kt + (tid - 64) * 4);
    };

    issue_stage(0);
    cp_commit();
    __syncthreads();                                // qs visible

    // per-thread q registers (h-producer role: row hm, k-half kh)
    const int hm = tid & 127, kh = tid >> 7;
    float ql[8];
#pragma unroll
    for (int i = 0; i < 8; ++i) ql[i] = qs[hm * 8 + i];

    // ldmatrix per-thread address offsets (within a tile)
    uint32_t aoff[4], boff[2];
#pragma unroll
    for (int i = 0; i < 4; ++i)
        aoff[i] = (wm * 64 + i * 16 + (lane & 15)) * RS + (lane >> 4) * 16;
#pragma unroll
    for (int j = 0; j < 2; ++j)
        boff[j] = (wn * 32 + j * 16 + (lane & 7) + ((lane >> 4) & 1) * 8) * RS +
                  ((lane >> 3) & 1) * 16;

    float acc[4][4][4];
#pragma unroll
    for (int i = 0; i < 4; ++i)
#pragma unroll
        for (int j = 0; j < 4; ++j)
#pragma unroll
            for (int r = 0; r < 4; ++r) acc[i][j][r] = 0.0f;

    // ================= main loop =================
    for (int t = 0; t < NTILE; ++t) {
        const int buf = t & 1;
        const uint32_t st = sb + OFF_ST + buf * STAGE;
        char* stp = smem + OFF_ST + buf * STAGE;

        cp_wait_all();                  // stage t data arrived
        __syncthreads();                // S1: + all ldsm of t-1 complete

        if (t + 1 < NTILE) issue_stage(t + 1);   // writes buffer !buf (safe)
        cp_commit();

        // ---- h tile: h = relu(q.W1+b1), split bf16 hi/lo ----
        {
            const float* w1f = (const float*)(stp + S_W1);
            const float* b1f = (const float*)(stp + S_B1);
            uint32_t vh[8], vl[8];
#pragma unroll
            for (int kk = 0; kk < 16; kk += 2) {
                float h2[2];
#pragma unroll
                for (int u = 0; u < 2; ++u) {
                    int k = kh * 16 + kk + u;
                    float4 wa = *(const float4*)(w1f + k * 8);
                    float4 wb = *(const float4*)(w1f + k * 8 + 4);
                    float s = b1f[k];
                    s = fmaf(ql[0], wa.x, s); s = fmaf(ql[1], wa.y, s);
                    s = fmaf(ql[2], wa.z, s); s = fmaf(ql[3], wa.w, s);
                    s = fmaf(ql[4], wb.x, s); s = fmaf(ql[5], wb.y, s);
                    s = fmaf(ql[6], wb.z, s); s = fmaf(ql[7], wb.w, s);
                    h2[u] = fmaxf(s, 0.0f);
                }
                __nv_bfloat162 ph, pl;
                ph.x = __float2bfloat16(h2[0]);
                ph.y = __float2bfloat16(h2[1]);
                pl.x = __float2bfloat16(h2[0] - __bfloat162float(ph.x));
                pl.y = __float2bfloat16(h2[1] - __bfloat162float(ph.y));
                vh[kk >> 1] = *(uint32_t*)&ph;
                vl[kk >> 1] = *(uint32_t*)&pl;
            }
            char* hd = stp + S_AHI + hm * RS + kh * 32;
            char* ld_ = stp + S_ALO + hm * RS + kh * 32;
            *(uint4*)hd        = make_uint4(vh[0], vh[1], vh[2], vh[3]);
            *(uint4*)(hd + 16) = make_uint4(vh[4], vh[5], vh[6], vh[7]);
            *(uint4*)ld_        = make_uint4(vl[0], vl[1], vl[2], vl[3]);
            *(uint4*)(ld_ + 16) = make_uint4(vl[4], vl[5], vl[6], vl[7]);
        }
        __syncthreads();                // S2: h tile visible

        // ---- 3-pass MMA over this K-tile ----
#pragma unroll
        for (int ks = 0; ks < 2; ++ks) {
            uint32_t ahi[4][4], alo[4][4], bhi[4][2], blo[4][2];
#pragma unroll
            for (int i = 0; i < 4; ++i) {
                ldsm_x4(st + S_AHI + aoff[i] + ks * 32, ahi[i]);
                ldsm_x4(st + S_ALO + aoff[i] + ks * 32, alo[i]);
            }
#pragma unroll
            for (int j = 0; j < 2; ++j) {
                uint32_t r[4];
                ldsm_x4(st + S_BHI + boff[j] + ks * 32, r);
                bhi[j * 2][0] = r[0]; bhi[j * 2][1] = r[1];
                bhi[j * 2 + 1][0] = r[2]; bhi[j * 2 + 1][1] = r[3];
                ldsm_x4(st + S_BLO + boff[j] + ks * 32, r);
                blo[j * 2][0] = r[0]; blo[j * 2][1] = r[1];
                blo[j * 2 + 1][0] = r[2]; blo[j * 2 + 1][1] = r[3];
            }
#pragma unroll
            for (int i = 0; i < 4; ++i)
#pragma unroll
                for (int j = 0; j < 4; ++j) {
                    mma_bf16(acc[i][j], ahi[i], bhi[j]);
                    mma_bf16(acc[i][j], ahi[i], blo[j]);
                    mma_bf16(acc[i][j], alo[i], bhi[j]);
                }
        }
    }

    // ================= epilogue: +b2, store =================
#pragma unroll
    for (int i = 0; i < 4; ++i) {
        const int r0 = m0 + wm * 64 + i * 16 + (lane >> 2);
#pragma unroll
        for (int j = 0; j < 4; ++j) {
            const int c0 = n0 + wn * 32 + j * 8 + 2 * (lane & 3);
            float2 bb = *(const float2*)(b2 + c0);
            float2 v0, v1;
            v0.x = acc[i][j][0] + bb.x; v0.y = acc[i][j][1] + bb.y;
            v1.x = acc[i][j][2] + bb.x; v1.y = acc[i][j][3] + bb.y;
            *(float2*)(out + (size_t)r0 * EMB + c0)       = v0;
            *(float2*)(out + (size_t)(r0 + 8) * EMB + c0) = v1;
        }
    }
}

// ---------------------------------------------------------------------------
extern "C" void kernel_launch(void* const* d_in, const int* in_sizes, int n_in,
                              void* d_out, int out_size) {
    const float* x     = (const float*)d_in[0];
    const float* theta = (const float*)d_in[1];
    const float* W1    = (const float*)d_in[2];
    const float* b1    = (const float*)d_in[3];
    const float* W2    = (const float*)d_in[4];
    const float* b2    = (const float*)d_in[5];
    float* out = (float*)d_out;

    cudaFuncSetAttribute(ffq_mma_kernel,
                         cudaFuncAttributeMaxDynamicSharedMemorySize, SMEM_BYTES);

    w2cvt_kernel<<<(EMB * FFN / 4) / 256, 256>>>(W2);

    dim3 grid(EMB / BN, Mtot / BM);   // (8, 128)
    ffq_mma_kernel<<<grid, NTH, SMEM_BYTES>>>(x, theta, W1, b1, b2, out);
}

// round 5
// speedup vs baseline: 2.2459x; 1.0005x over previous
#include <cuda_runtime.h>
#include <cuda_bf16.h>
#include <cstdint>

// ============================================================================
// FeedForwardQuantum via mma.sync bf16x3 (hi/lo error compensation).
//   q[m,i]   = cos(x[m,i]) * cos(theta[i]), i<8
//   h[m,f]   = relu(q @ W1^T + b1)   (recomputed per K-tile, split bf16 hi/lo)
//   out[m,e] = h @ W2^T + b2         (3 HMMA passes: hh + h_hi*W_lo + h_lo*W_hi)
// tcgen05 is unavailable (harness PTX targets sm_103 baseline), so this uses
// mma.sync.m16n8k16 + ldmatrix + cp.async, all baseline-PTX legal.
// ============================================================================

namespace {
constexpr int Mtot = 16384, EMB = 1024, FFN = 4096, NQ = 8;
constexpr int BM = 128, BN = 128, BK = 32;
constexpr int NTILE = FFN / BK;     // 128
constexpr int NTH = 256;            // 8 warps, 2x4 warp grid, 64x32 warp tiles
constexpr int RS = 80;              // smem row stride (bytes): 64B data + 16B pad

// per-stage smem offsets (bytes)
constexpr int S_W1  = 0;            // 32*8*4      = 1024
constexpr int S_B1  = 1024;         // 32*4        = 128
constexpr int S_AHI = 1152;         // 128*80      = 10240
constexpr int S_ALO = 11392;
constexpr int S_BHI = 21632;
constexpr int S_BLO = 31872;
constexpr int STAGE = 42112;

constexpr int OFF_Q  = 0;           // 128*8*4 = 4096
constexpr int OFF_ST = 4096;
constexpr int SMEM_BYTES = OFF_ST + 2 * STAGE;   // 88320
}

// W2 pre-split into bf16 hi/lo (device scratch, filled by pre-kernel)
__device__ __nv_bfloat16 g_w2hi[(size_t)EMB * FFN];
__device__ __nv_bfloat16 g_w2lo[(size_t)EMB * FFN];

// ---------------------------------------------------------------------------
__device__ __forceinline__ uint32_t smem_u32(const void* p) {
    uint32_t a;
    asm("{ .reg .u64 t; cvta.to.shared.u64 t, %1; cvt.u32.u64 %0, t; }"
        : "=r"(a) : "l"(p));
    return a;
}
__device__ __forceinline__ void cp16(uint32_t dst, const void* src) {
    asm volatile("cp.async.cg.shared.global [%0], [%1], 16;\n"
                 :: "r"(dst), "l"(src) : "memory");
}
__device__ __forceinline__ void cp_commit() {
    asm volatile("cp.async.commit_group;\n" ::: "memory");
}
__device__ __forceinline__ void cp_wait_all() {
    asm volatile("cp.async.wait_group 0;\n" ::: "memory");
}
__device__ __forceinline__ void ldsm_x4(uint32_t a, uint32_t* r) {
    asm volatile("ldmatrix.sync.aligned.m8n8.x4.shared.b16 {%0,%1,%2,%3}, [%4];\n"
                 : "=r"(r[0]), "=r"(r[1]), "=r"(r[2]), "=r"(r[3]) : "r"(a));
}
__device__ __forceinline__ void mma_bf16(float* c, const uint32_t* a,
                                         const uint32_t* b) {
    asm volatile(
        "mma.sync.aligned.m16n8k16.row.col.f32.bf16.bf16.f32 "
        "{%0,%1,%2,%3}, {%4,%5,%6,%7}, {%8,%9}, {%0,%1,%2,%3};\n"
        : "+f"(c[0]), "+f"(c[1]), "+f"(c[2]), "+f"(c[3])
        : "r"(a[0]), "r"(a[1]), "r"(a[2]), "r"(a[3]), "r"(b[0]), "r"(b[1]));
}

// ---------------------------------------------------------------------------
// pre-kernel: W2 fp32 -> bf16 hi/lo
// ---------------------------------------------------------------------------
__global__ void w2cvt_kernel(const float* __restrict__ w2) {
    size_t i = (size_t)blockIdx.x * blockDim.x + threadIdx.x;  // float4 index
    float4 v = __ldg((const float4*)w2 + i);
    __nv_bfloat162 ph0, ph1, pl0, pl1;
    ph0.x = __float2bfloat16(v.x); ph0.y = __float2bfloat16(v.y);
    ph1.x = __float2bfloat16(v.z); ph1.y = __float2bfloat16(v.w);
    pl0.x = __float2bfloat16(v.x - __bfloat162float(ph0.x));
    pl0.y = __float2bfloat16(v.y - __bfloat162float(ph0.y));
    pl1.x = __float2bfloat16(v.z - __bfloat162float(ph1.x));
    pl1.y = __float2bfloat16(v.w - __bfloat162float(ph1.y));
    ((uint2*)g_w2hi)[i] = make_uint2(*(uint32_t*)&ph0, *(uint32_t*)&ph1);
    ((uint2*)g_w2lo)[i] = make_uint2(*(uint32_t*)&pl0, *(uint32_t*)&pl1);
}

// ---------------------------------------------------------------------------
// main fused kernel
// ---------------------------------------------------------------------------
__global__ __launch_bounds__(NTH, 1)
void ffq_mma_kernel(const float* __restrict__ x, const float* __restrict__ theta,
                    const float* __restrict__ W1, const float* __restrict__ b1,
                    const float* __restrict__ b2, float* __restrict__ out) {
    extern __shared__ char smem[];
    const uint32_t sb = smem_u32(smem);
    const int tid = threadIdx.x, lane = tid & 31, wid = tid >> 5;
    const int wm = wid >> 2, wn = wid & 3;          // 2x4 warp grid
    const int m0 = blockIdx.y * BM, n0 = blockIdx.x * BN;

    // ---- q tile ----
    float* qs = (float*)(smem + OFF_Q);
    for (int e = tid; e < BM * NQ; e += NTH) {
        int m = e >> 3, i = e & 7;
        qs[e] = cosf(__ldg(x + (size_t)(m0 + m) * EMB + i)) *
                cosf(__ldg(theta + i));
    }

    // ---- cp.async stage issue (W2 hi/lo tile + W1 chunk + b1 chunk) ----
    auto issue_stage = [&](int t) {
        const uint32_t st = sb + OFF_ST + (t & 1) * STAGE;
        const int kt = t * BK;
#pragma unroll
        for (int p = 0; p < 2; ++p) {
            int c = tid + p * 256;                  // 0..511
            int row = c >> 2, seg = c & 3;
            size_t gi = (size_t)(n0 + row) * FFN + kt + seg * 8;
            uint32_t so = row * RS + seg * 16;
            cp16(st + S_BHI + so, g_w2hi + gi);
            cp16(st + S_BLO + so, g_w2lo + gi);
        }
        if (tid < 64)
            cp16(st + S_W1 + tid * 16, W1 + (size_t)kt * NQ + tid * 4);
        else if (tid < 72)
            cp16(st + S_B1 + (tid - 64) * 16, b1 + kt + (tid - 64) * 4);
    };

    issue_stage(0);
    cp_commit();
    __syncthreads();                                // qs visible

    // per-thread q registers (h-producer role: row hm, k-half kh)
    const int hm = tid & 127, kh = tid >> 7;
    float ql[8];
#pragma unroll
    for (int i = 0; i < 8; ++i) ql[i] = qs[hm * 8 + i];

    // ldmatrix per-thread address offsets (within a tile)
    uint32_t aoff[4], boff[2];
#pragma unroll
    for (int i = 0; i < 4; ++i)
        aoff[i] = (wm * 64 + i * 16 + (lane & 15)) * RS + (lane >> 4) * 16;
#pragma unroll
    for (int j = 0; j < 2; ++j)
        boff[j] = (wn * 32 + j * 16 + (lane & 7) + ((lane >> 4) & 1) * 8) * RS +
                  ((lane >> 3) & 1) * 16;

    float acc[4][4][4];
#pragma unroll
    for (int i = 0; i < 4; ++i)
#pragma unroll
        for (int j = 0; j < 4; ++j)
#pragma unroll
            for (int r = 0; r < 4; ++r) acc[i][j][r] = 0.0f;

    // ================= main loop =================
    for (int t = 0; t < NTILE; ++t) {
        const int buf = t & 1;
        const uint32_t st = sb + OFF_ST + buf * STAGE;
        char* stp = smem + OFF_ST + buf * STAGE;

        cp_wait_all();                  // stage t data arrived
        __syncthreads();                // S1: + all ldsm of t-1 complete

        if (t + 1 < NTILE) issue_stage(t + 1);   // writes buffer !buf (safe)
        cp_commit();

        // ---- h tile: h = relu(q.W1+b1), split bf16 hi/lo ----
        {
            const float* w1f = (const float*)(stp + S_W1);
            const float* b1f = (const float*)(stp + S_B1);
            uint32_t vh[8], vl[8];
#pragma unroll
            for (int kk = 0; kk < 16; kk += 2) {
                float h2[2];
#pragma unroll
                for (int u = 0; u < 2; ++u) {
                    int k = kh * 16 + kk + u;
                    float4 wa = *(const float4*)(w1f + k * 8);
                    float4 wb = *(const float4*)(w1f + k * 8 + 4);
                    float s = b1f[k];
                    s = fmaf(ql[0], wa.x, s); s = fmaf(ql[1], wa.y, s);
                    s = fmaf(ql[2], wa.z, s); s = fmaf(ql[3], wa.w, s);
                    s = fmaf(ql[4], wb.x, s); s = fmaf(ql[5], wb.y, s);
                    s = fmaf(ql[6], wb.z, s); s = fmaf(ql[7], wb.w, s);
                    h2[u] = fmaxf(s, 0.0f);
                }
                __nv_bfloat162 ph, pl;
                ph.x = __float2bfloat16(h2[0]);
                ph.y = __float2bfloat16(h2[1]);
                pl.x = __float2bfloat16(h2[0] - __bfloat162float(ph.x));
                pl.y = __float2bfloat16(h2[1] - __bfloat162float(ph.y));
                vh[kk >> 1] = *(uint32_t*)&ph;
                vl[kk >> 1] = *(uint32_t*)&pl;
            }
            char* hd = stp + S_AHI + hm * RS + kh * 32;
            char* ld_ = stp + S_ALO + hm * RS + kh * 32;
            *(uint4*)hd        = make_uint4(vh[0], vh[1], vh[2], vh[3]);
            *(uint4*)(hd + 16) = make_uint4(vh[4], vh[5], vh[6], vh[7]);
            *(uint4*)ld_        = make_uint4(vl[0], vl[1], vl[2], vl[3]);
            *(uint4*)(ld_ + 16) = make_uint4(vl[4], vl[5], vl[6], vl[7]);
        }
        __syncthreads();                // S2: h tile visible

        // ---- 3-pass MMA over this K-tile ----
#pragma unroll
        for (int ks = 0; ks < 2; ++ks) {
            uint32_t ahi[4][4], alo[4][4], bhi[4][2], blo[4][2];
#pragma unroll
            for (int i = 0; i < 4; ++i) {
                ldsm_x4(st + S_AHI + aoff[i] + ks * 32, ahi[i]);
                ldsm_x4(st + S_ALO + aoff[i] + ks * 32, alo[i]);
            }
#pragma unroll
            for (int j = 0; j < 2; ++j) {
                uint32_t r[4];
                ldsm_x4(st + S_BHI + boff[j] + ks * 32, r);
                bhi[j * 2][0] = r[0]; bhi[j * 2][1] = r[1];
                bhi[j * 2 + 1][0] = r[2]; bhi[j * 2 + 1][1] = r[3];
                ldsm_x4(st + S_BLO + boff[j] + ks * 32, r);
                blo[j * 2][0] = r[0]; blo[j * 2][1] = r[1];
                blo[j * 2 + 1][0] = r[2]; blo[j * 2 + 1][1] = r[3];
            }
#pragma unroll
            for (int i = 0; i < 4; ++i)
#pragma unroll
                for (int j = 0; j < 4; ++j) {
                    mma_bf16(acc[i][j], ahi[i], bhi[j]);
                    mma_bf16(acc[i][j], ahi[i], blo[j]);
                    mma_bf16(acc[i][j], alo[i], bhi[j]);
                }
        }
    }

    // ================= epilogue: +b2, store =================
#pragma unroll
    for (int i = 0; i < 4; ++i) {
        const int r0 = m0 + wm * 64 + i * 16 + (lane >> 2);
#pragma unroll
        for (int j = 0; j < 4; ++j) {
            const int c0 = n0 + wn * 32 + j * 8 + 2 * (lane & 3);
            float2 bb = *(const float2*)(b2 + c0);
            float2 v0, v1;
            v0.x = acc[i][j][0] + bb.x; v0.y = acc[i][j][1] + bb.y;
            v1.x = acc[i][j][2] + bb.x; v1.y = acc[i][j][3] + bb.y;
            *(float2*)(out + (size_t)r0 * EMB + c0)       = v0;
            *(float2*)(out + (size_t)(r0 + 8) * EMB + c0) = v1;
        }
    }
}

// ---------------------------------------------------------------------------
extern "C" void kernel_launch(void* const* d_in, const int* in_sizes, int n_in,
                              void* d_out, int out_size) {
    const float* x     = (const float*)d_in[0];
    const float* theta = (const float*)d_in[1];
    const float* W1    = (const float*)d_in[2];
    const float* b1    = (const float*)d_in[3];
    const float* W2    = (const float*)d_in[4];
    const float* b2    = (const float*)d_in[5];
    float* out = (float*)d_out;

    cudaFuncSetAttribute(ffq_mma_kernel,
                         cudaFuncAttributeMaxDynamicSharedMemorySize, SMEM_BYTES);

    w2cvt_kernel<<<(EMB * FFN / 4) / 256, 256>>>(W2);

    dim3 grid(EMB / BN, Mtot / BM);   // (8, 128)
    ffq_mma_kernel<<<grid, NTH, SMEM_BYTES>>>(x, theta, W1, b1, b2, out);
}